// round 5
// baseline (speedup 1.0000x reference)
#include <cuda_runtime.h>
#include <cuda_fp16.h>
#include <cstdint>

// ---------------------------------------------------------------------------
// STGN_LSTM (no effective recurrence -> pointwise map of X[:,4,:]).
// MUFU-bound => pack 2 batch rows per thread, f16x2 datapath with
// tanh.approx.f16x2 (halves MUFU instruction count).
//   per unit n (both rows in the two f16 halves):
//     z1' = 0.5*zi   (pre-scaled weights)        -> tanh -> ig = 0.5t+0.5
//     z2' = 0.5*zT   (pre-scaled weights)        -> tanh
//     Tg*dt = t2*(0.5dt) + 0.5dt                 -> tanh -> u
//     cc = ig*u                                  -> tanh -> h
//   logit accumulated in fp32; final sigmoid precise f32.
// ---------------------------------------------------------------------------

struct alignas(16) UT { __half2 a, b, c, d; };                 // 0.5*Wix0, 0.5*Wix1, 0.5*biSum, 0.5*WTt
struct alignas(16) VT { __half2 a, b, c; float w; };           // 0.5*WTx0, 0.5*WTx1, 0.5*bTSum, clsw(f32)

static __device__ __forceinline__ __half2 tanh2(__half2 x) {
    uint32_t r, i = *(const uint32_t*)&x;
    asm("tanh.approx.f16x2 %0, %1;" : "=r"(r) : "r"(i));
    return *(const __half2*)&r;
}
static __device__ __forceinline__ __half2 bcast(float v) {
    return __float2half2_rn(v);
}

__global__ void __launch_bounds__(256)
stgn_kernel(const float* __restrict__ X,
            const float* __restrict__ Wix, const float* __restrict__ Wix_b,
            const float* __restrict__ Wih_b, const float* __restrict__ bi,
            const float* __restrict__ WTx, const float* __restrict__ WTx_b,
            const float* __restrict__ WTh_b,
            const float* __restrict__ WTt, const float* __restrict__ WTt_b,
            const float* __restrict__ bT,
            const float* __restrict__ clsw, const float* __restrict__ clsb,
            float* __restrict__ out, int npairs) {
    __shared__ UT tabU[64];
    __shared__ VT tabV[64];
    __shared__ float cbS;

    const int tid = threadIdx.x;
    if (tid < 64) {
        const int n = tid;
        UT u;
        u.a = bcast(0.5f * Wix[2 * n]);
        u.b = bcast(0.5f * Wix[2 * n + 1]);
        u.c = bcast(0.5f * (Wih_b[n] + Wix_b[n] + bi[n]));
        u.d = bcast(0.5f * WTt[n]);
        tabU[n] = u;
        VT v;
        v.a = bcast(0.5f * WTx[2 * n]);
        v.b = bcast(0.5f * WTx[2 * n + 1]);
        v.c = bcast(0.5f * (WTh_b[n] + WTx_b[n] + WTt_b[n] + bT[n]));
        v.w = clsw[n];
        tabV[n] = v;
    }
    if (tid == 0) cbS = clsb[0];
    __syncthreads();

    const int pid = blockIdx.x * 256 + tid;
    if (pid >= npairs) return;

    // two adjacent batch rows; x at t=4 lives at float offsets 12..14 of each
    const float* xr = X + (size_t)pid * 30 + 12;
    const float x0a = xr[0],  x1a = xr[1],  dta = xr[2];
    const float x0b = xr[15], x1b = xr[16], dtb = xr[17];

    const __half2 x0p = __floats2half2_rn(x0a, x0b);
    const __half2 x1p = __floats2half2_rn(x1a, x1b);
    const __half2 dtp = __floats2half2_rn(dta, dtb);
    const __half2 dth = __floats2half2_rn(0.5f * dta, 0.5f * dtb);
    const __half2 H05 = __float2half2_rn(0.5f);

    float lg0 = cbS, lg1 = cbS;

#pragma unroll 8
    for (int n = 0; n < 64; n++) {
        const UT u = tabU[n];
        const VT v = tabV[n];

        const __half2 z1 = __hfma2(u.a, x0p, __hfma2(u.b, x1p, u.c));      // 0.5*zi
        const __half2 z2 = __hfma2(v.a, x0p, __hfma2(v.b, x1p,
                                    __hfma2(u.d, dtp, v.c)));              // 0.5*zT
        const __half2 t1 = tanh2(z1);
        const __half2 t2 = tanh2(z2);
        const __half2 ig = __hfma2(t1, H05, H05);                          // sig(zi)
        const __half2 ta = __hfma2(t2, dth, dth);                          // sig(zT)*dt
        const __half2 uu = tanh2(ta);
        const __half2 cc = __hmul2(ig, uu);
        const __half2 hh = tanh2(cc);

        const float2 hf = __half22float2(hh);
        lg0 = fmaf(hf.x, v.w, lg0);
        lg1 = fmaf(hf.y, v.w, lg1);
    }

    // precise output sigmoid, adjacent rows -> one 8B store
    const float o0 = __fdividef(1.0f, 1.0f + __expf(-lg0));
    const float o1 = __fdividef(1.0f, 1.0f + __expf(-lg1));
    *(float2*)(out + (size_t)pid * 2) = make_float2(o0, o1);
}

extern "C" void kernel_launch(void* const* d_in, const int* in_sizes, int n_in,
                              void* d_out, int out_size) {
    const float* X      = (const float*)d_in[0];
    const float* Wih_b  = (const float*)d_in[7];
    const float* Wix_w  = (const float*)d_in[8];
    const float* Wix_b  = (const float*)d_in[9];
    const float* bi     = (const float*)d_in[10];
    const float* WTh_b  = (const float*)d_in[12];
    const float* WTx_w  = (const float*)d_in[13];
    const float* WTx_b  = (const float*)d_in[14];
    const float* WTt_w  = (const float*)d_in[15];
    const float* WTt_b  = (const float*)d_in[16];
    const float* bT     = (const float*)d_in[17];
    const float* cls_w  = (const float*)d_in[18];
    const float* cls_b  = (const float*)d_in[19];

    const int nrows  = in_sizes[0] / 15;
    const int npairs = nrows / 2;
    const int blocks = (npairs + 255) / 256;

    stgn_kernel<<<blocks, 256>>>(
        X, Wix_w, Wix_b, Wih_b, bi,
        WTx_w, WTx_b, WTh_b, WTt_w, WTt_b, bT,
        cls_w, cls_b, (float*)d_out, npairs);
}

// round 6
// speedup vs baseline: 1.0692x; 1.0692x over previous
#include <cuda_runtime.h>
#include <cstdint>

// ---------------------------------------------------------------------------
// STGN_LSTM == pointwise map of X[:,4,:] (reference never updates h/c state).
// MUFU-VALUE-throughput bound (f16x2 tanh is half-rate per inst => no gain
// from packing). Strategy: 2 rows/thread on the packed fp32 pipe
// (fma.rn.f32x2), tanh values cut 4 -> 3 per unit by computing
// h = tanh(cc), |cc|<=1, on the FMA pipe via the exact Pade [5/4]
//   tanh(x) ~= x(945+105x^2+x^4)/(945+420x^2+15x^4)   (err ~3e-8 on [-1,1])
// with an FMA-only Newton reciprocal (den in [945,1380], linear init + 2 it).
// Remaining 3 sites (unbounded args) use tanh.approx.f32 at full value rate.
// ---------------------------------------------------------------------------

typedef unsigned long long u64;

static __device__ __forceinline__ float tanh_mufu(float x) {
    float y; asm("tanh.approx.f32 %0, %1;" : "=f"(y) : "f"(x)); return y;
}
static __device__ __forceinline__ u64 pk(float lo, float hi) {
    u64 r; asm("mov.b64 %0, {%1, %2};" : "=l"(r) : "f"(lo), "f"(hi)); return r;
}
static __device__ __forceinline__ void upk(float& lo, float& hi, u64 v) {
    asm("mov.b64 {%0, %1}, %2;" : "=f"(lo), "=f"(hi) : "l"(v));
}
static __device__ __forceinline__ u64 fma2(u64 a, u64 b, u64 c) {
    u64 d; asm("fma.rn.f32x2 %0, %1, %2, %3;" : "=l"(d) : "l"(a), "l"(b), "l"(c));
    return d;
}
static __device__ __forceinline__ u64 mul2(u64 a, u64 b) {
    u64 d; asm("mul.rn.f32x2 %0, %1, %2;" : "=l"(d) : "l"(a), "l"(b)); return d;
}
static __device__ __forceinline__ u64 add2(u64 a, u64 b) {
    u64 d; asm("add.rn.f32x2 %0, %1, %2;" : "=l"(d) : "l"(a), "l"(b)); return d;
}
static __device__ __forceinline__ u64 tanh2_mufu(u64 v) {
    float a, b; upk(a, b, v);
    return pk(tanh_mufu(a), tanh_mufu(b));
}

__global__ void __launch_bounds__(256)
stgn_kernel(const float* __restrict__ X,
            const float* __restrict__ Wix, const float* __restrict__ Wix_b,
            const float* __restrict__ Wih_b, const float* __restrict__ bi,
            const float* __restrict__ WTx, const float* __restrict__ WTx_b,
            const float* __restrict__ WTh_b,
            const float* __restrict__ WTt, const float* __restrict__ WTt_b,
            const float* __restrict__ bT,
            const float* __restrict__ clsw, const float* __restrict__ clsb,
            float* __restrict__ out, int npairs) {
    __shared__ float4 Tb[64][4];
    __shared__ float  cbS;

    const int tid = threadIdx.x;
    if (tid < 64) {
        const int n = tid;
        const float A = 0.5f * Wix[2 * n];
        const float B = 0.5f * Wix[2 * n + 1];
        const float C = 0.5f * (Wih_b[n] + Wix_b[n] + bi[n]);
        const float D = 0.5f * WTt[n];
        const float E = 0.5f * WTx[2 * n];
        const float F = 0.5f * WTx[2 * n + 1];
        const float G = 0.5f * (WTh_b[n] + WTx_b[n] + WTt_b[n] + bT[n]);
        const float W = -clsw[n];               // negated: folds Newton sign
        Tb[n][0] = make_float4(A, A, B, B);
        Tb[n][1] = make_float4(C, C, D, D);
        Tb[n][2] = make_float4(E, E, F, F);
        Tb[n][3] = make_float4(G, G, W, W);
    }
    if (tid == 0) cbS = clsb[0];
    __syncthreads();

    const int pid = blockIdx.x * 256 + tid;
    if (pid >= npairs) return;

    // two adjacent rows; x(t=4) at float offsets 12..14 of each 15-float row
    const float* xr = X + (size_t)pid * 30 + 12;
    const float x0a = xr[0],  x1a = xr[1],  dta = xr[2];
    const float x0b = xr[15], x1b = xr[16], dtb = xr[17];

    const u64 x0p = pk(x0a, x0b);
    const u64 x1p = pk(x1a, x1b);
    const u64 dtp = pk(dta, dtb);
    const u64 dth = pk(0.5f * dta, 0.5f * dtb);
    const u64 h05 = pk(0.5f, 0.5f);

    // Pade / Newton constants
    const u64 c105 = pk(105.0f, 105.0f);
    const u64 c945 = pk(945.0f, 945.0f);
    const u64 c420 = pk(420.0f, 420.0f);
    const u64 c15  = pk(15.0f, 15.0f);
    const u64 cm2  = pk(-2.0f, -2.0f);
    const u64 c2   = pk(2.0f, 2.0f);
    const u64 cRA  = pk(1.0582011e-3f, 1.0582011e-3f);   // 1/945
    const u64 cRB  = pk(-3.3356338e-4f, -3.3356338e-4f); // (1/1380-1/945)

    const float cb = cbS;
    u64 lg = pk(cb, cb);

#pragma unroll 8
    for (int n = 0; n < 64; n++) {
        const float4 q0 = Tb[n][0];
        const float4 q1 = Tb[n][1];
        const float4 q2 = Tb[n][2];
        const float4 q3 = Tb[n][3];
        const u64 Ap = pk(q0.x, q0.y), Bp = pk(q0.z, q0.w);
        const u64 Cp = pk(q1.x, q1.y), Dp = pk(q1.z, q1.w);
        const u64 Ep = pk(q2.x, q2.y), Fp = pk(q2.z, q2.w);
        const u64 Gp = pk(q3.x, q3.y), Wp = pk(q3.z, q3.w);

        const u64 z1 = fma2(Ap, x0p, fma2(Bp, x1p, Cp));              // 0.5*zi
        const u64 z2 = fma2(Ep, x0p, fma2(Fp, x1p, fma2(Dp, dtp, Gp))); // 0.5*zT

        const u64 t1 = tanh2_mufu(z1);           // MUFU x2
        const u64 t2 = tanh2_mufu(z2);           // MUFU x2
        const u64 ig = fma2(t1, h05, h05);       // sig(zi)
        const u64 ta = fma2(t2, dth, dth);       // sig(zT)*dt
        const u64 uu = tanh2_mufu(ta);           // MUFU x2
        const u64 cc = mul2(ig, uu);             // |cc| <= 1

        // h = tanh(cc) on FMA pipe: Pade[5/4] + Newton reciprocal
        const u64 s  = mul2(cc, cc);
        const u64 nt = fma2(add2(s, c105), s, c945);        // s^2+105s+945
        const u64 nx = mul2(nt, cc);                        // numerator * x
        const u64 dn = fma2(fma2(s, c15, c420), s, c945);   // 15s^2+420s+945
        u64 r  = fma2(s, cRB, cRA);                         // ~1/dn (3.3%)
        u64 e  = fma2(dn, r, cm2); r = mul2(r, e);          // r = -rho1
        e = fma2(dn, r, c2);       r = mul2(r, e);          // r = -rho2 ~ -1/dn
        // (-h) = nx * r ;  logit += (-h)*(-w)
        lg = fma2(mul2(nx, r), Wp, lg);
    }

    float lg0, lg1; upk(lg0, lg1, lg);
    const float o0 = __fdividef(1.0f, 1.0f + __expf(-lg0));
    const float o1 = __fdividef(1.0f, 1.0f + __expf(-lg1));
    *(float2*)(out + (size_t)pid * 2) = make_float2(o0, o1);
}

extern "C" void kernel_launch(void* const* d_in, const int* in_sizes, int n_in,
                              void* d_out, int out_size) {
    const float* X      = (const float*)d_in[0];
    const float* Wih_b  = (const float*)d_in[7];
    const float* Wix_w  = (const float*)d_in[8];
    const float* Wix_b  = (const float*)d_in[9];
    const float* bi     = (const float*)d_in[10];
    const float* WTh_b  = (const float*)d_in[12];
    const float* WTx_w  = (const float*)d_in[13];
    const float* WTx_b  = (const float*)d_in[14];
    const float* WTt_w  = (const float*)d_in[15];
    const float* WTt_b  = (const float*)d_in[16];
    const float* bT     = (const float*)d_in[17];
    const float* cls_w  = (const float*)d_in[18];
    const float* cls_b  = (const float*)d_in[19];

    const int nrows  = in_sizes[0] / 15;
    const int npairs = nrows / 2;
    const int blocks = (npairs + 255) / 256;

    stgn_kernel<<<blocks, 256>>>(
        X, Wix_w, Wix_b, Wih_b, bi,
        WTx_w, WTx_b, WTh_b, WTt_w, WTt_b, bT,
        cls_w, cls_b, (float*)d_out, npairs);
}

// round 7
// speedup vs baseline: 1.1393x; 1.0656x over previous
#include <cuda_runtime.h>
#include <cstdint>

// ---------------------------------------------------------------------------
// STGN_LSTM == pointwise map of X[:,4,:].
// r6 evidence: no pipe saturated (MUFU 70%, FMA 53%, issue 47%, L1 45%) —
// the Pade+Newton h-tanh overloaded FMA/issue. This round:
//   h = tanh(cc), |cc|<=1  ->  cc * P4(cc^2)   (Chebyshev, ~5e-5 abs err,
//   7 FFMA2 instead of 15)  — MUFU stays 3 values/row (binding, ~23.6us).
// 128-thread CTAs for wave balance (grid 2048, ~14 CTAs/SM resident).
// ---------------------------------------------------------------------------

typedef unsigned long long u64;

static __device__ __forceinline__ float tanh_mufu(float x) {
    float y; asm("tanh.approx.f32 %0, %1;" : "=f"(y) : "f"(x)); return y;
}
static __device__ __forceinline__ u64 pk(float lo, float hi) {
    u64 r; asm("mov.b64 %0, {%1, %2};" : "=l"(r) : "f"(lo), "f"(hi)); return r;
}
static __device__ __forceinline__ void upk(float& lo, float& hi, u64 v) {
    asm("mov.b64 {%0, %1}, %2;" : "=f"(lo), "=f"(hi) : "l"(v));
}
static __device__ __forceinline__ u64 fma2(u64 a, u64 b, u64 c) {
    u64 d; asm("fma.rn.f32x2 %0, %1, %2, %3;" : "=l"(d) : "l"(a), "l"(b), "l"(c));
    return d;
}
static __device__ __forceinline__ u64 mul2(u64 a, u64 b) {
    u64 d; asm("mul.rn.f32x2 %0, %1, %2;" : "=l"(d) : "l"(a), "l"(b)); return d;
}
static __device__ __forceinline__ u64 tanh2_mufu(u64 v) {
    float a, b; upk(a, b, v);
    return pk(tanh_mufu(a), tanh_mufu(b));
}

__global__ void __launch_bounds__(128)
stgn_kernel(const float* __restrict__ X,
            const float* __restrict__ Wix, const float* __restrict__ Wix_b,
            const float* __restrict__ Wih_b, const float* __restrict__ bi,
            const float* __restrict__ WTx, const float* __restrict__ WTx_b,
            const float* __restrict__ WTh_b,
            const float* __restrict__ WTt, const float* __restrict__ WTt_b,
            const float* __restrict__ bT,
            const float* __restrict__ clsw, const float* __restrict__ clsb,
            float* __restrict__ out, int npairs) {
    __shared__ float4 Tb[64][4];
    __shared__ float  cbS;

    const int tid = threadIdx.x;
    if (tid < 64) {
        const int n = tid;
        const float A = 0.5f * Wix[2 * n];
        const float B = 0.5f * Wix[2 * n + 1];
        const float C = 0.5f * (Wih_b[n] + Wix_b[n] + bi[n]);
        const float D = 0.5f * WTt[n];
        const float E = 0.5f * WTx[2 * n];
        const float F = 0.5f * WTx[2 * n + 1];
        const float G = 0.5f * (WTh_b[n] + WTx_b[n] + WTt_b[n] + bT[n]);
        const float W = clsw[n];
        Tb[n][0] = make_float4(A, A, B, B);
        Tb[n][1] = make_float4(C, C, D, D);
        Tb[n][2] = make_float4(E, E, F, F);
        Tb[n][3] = make_float4(G, G, W, W);
    }
    if (tid == 0) cbS = clsb[0];
    __syncthreads();

    const int pid = blockIdx.x * 128 + tid;
    if (pid >= npairs) return;

    // two adjacent rows; x(t=4) at float offsets 12..14 of each 15-float row
    const float* xr = X + (size_t)pid * 30 + 12;
    const float x0a = xr[0],  x1a = xr[1],  dta = xr[2];
    const float x0b = xr[15], x1b = xr[16], dtb = xr[17];

    const u64 x0p = pk(x0a, x0b);
    const u64 x1p = pk(x1a, x1b);
    const u64 dtp = pk(dta, dtb);
    const u64 dth = pk(0.5f * dta, 0.5f * dtb);
    const u64 h05 = pk(0.5f, 0.5f);

    // tanh(x) ~= x*P(x^2) on [-1,1], Chebyshev deg-4 in s (abs err ~5e-5)
    const u64 P0 = pk(0.9999900f, 0.9999900f);
    const u64 P1 = pk(-0.3322640f, -0.3322640f);
    const u64 P2 = pk(0.1274560f, 0.1274560f);
    const u64 P3 = pk(-0.0412160f, -0.0412160f);
    const u64 P4 = pk(0.0076800f, 0.0076800f);

    const float cb = cbS;
    u64 lg = pk(cb, cb);

#pragma unroll 8
    for (int n = 0; n < 64; n++) {
        const float4 q0 = Tb[n][0];
        const float4 q1 = Tb[n][1];
        const float4 q2 = Tb[n][2];
        const float4 q3 = Tb[n][3];
        const u64 Ap = pk(q0.x, q0.y), Bp = pk(q0.z, q0.w);
        const u64 Cp = pk(q1.x, q1.y), Dp = pk(q1.z, q1.w);
        const u64 Ep = pk(q2.x, q2.y), Fp = pk(q2.z, q2.w);
        const u64 Gp = pk(q3.x, q3.y), Wp = pk(q3.z, q3.w);

        const u64 z1 = fma2(Ap, x0p, fma2(Bp, x1p, Cp));                 // 0.5*zi
        const u64 z2 = fma2(Ep, x0p, fma2(Fp, x1p, fma2(Dp, dtp, Gp))); // 0.5*zT

        const u64 t1 = tanh2_mufu(z1);           // MUFU x2
        const u64 t2 = tanh2_mufu(z2);           // MUFU x2
        const u64 ig = fma2(t1, h05, h05);       // sig(zi)
        const u64 ta = fma2(t2, dth, dth);       // sig(zT)*dt
        const u64 uu = tanh2_mufu(ta);           // MUFU x2
        const u64 cc = mul2(ig, uu);             // |cc| <= 1

        // h = cc * P(cc^2)  (FMA pipe, 7 ops)
        const u64 s = mul2(cc, cc);
        u64 p = fma2(P4, s, P3);
        p = fma2(p, s, P2);
        p = fma2(p, s, P1);
        p = fma2(p, s, P0);
        const u64 h = mul2(p, cc);

        lg = fma2(h, Wp, lg);
    }

    float lg0, lg1; upk(lg0, lg1, lg);
    const float o0 = __fdividef(1.0f, 1.0f + __expf(-lg0));
    const float o1 = __fdividef(1.0f, 1.0f + __expf(-lg1));
    *(float2*)(out + (size_t)pid * 2) = make_float2(o0, o1);
}

extern "C" void kernel_launch(void* const* d_in, const int* in_sizes, int n_in,
                              void* d_out, int out_size) {
    const float* X      = (const float*)d_in[0];
    const float* Wih_b  = (const float*)d_in[7];
    const float* Wix_w  = (const float*)d_in[8];
    const float* Wix_b  = (const float*)d_in[9];
    const float* bi     = (const float*)d_in[10];
    const float* WTh_b  = (const float*)d_in[12];
    const float* WTx_w  = (const float*)d_in[13];
    const float* WTx_b  = (const float*)d_in[14];
    const float* WTt_w  = (const float*)d_in[15];
    const float* WTt_b  = (const float*)d_in[16];
    const float* bT     = (const float*)d_in[17];
    const float* cls_w  = (const float*)d_in[18];
    const float* cls_b  = (const float*)d_in[19];

    const int nrows  = in_sizes[0] / 15;
    const int npairs = nrows / 2;
    const int blocks = (npairs + 127) / 128;

    stgn_kernel<<<blocks, 128>>>(
        X, Wix_w, Wix_b, Wih_b, bi,
        WTx_w, WTx_b, WTh_b, WTt_w, WTt_b, bT,
        cls_w, cls_b, (float*)d_out, npairs);
}